// round 7
// baseline (speedup 1.0000x reference)
#include <cuda_runtime.h>

#define MAXR 100.0f

__device__ __forceinline__ float tanh_fast(float x) {
    float r;
    asm("tanh.approx.f32 %0, %1;" : "=f"(r) : "f"(x));
    return r;
}

// ---------------------------------------------------------------------------
// Fused kernel, per block = 8 consecutive same-row pixels (b, h, w0..w0+7).
// Tile stored channel-pair interleaved: tile2[c<32][pos] = (x[c], x[c+32])
// so the conv reads LDS.64 (27 loads/thread instead of 54 scalar).
// Weights repacked to wp[o][tap][c-pair] float2 for the same reason.
// Screen C0: logit_j = -|a|*mean_i(|d|*tanh(|a d|)) <= 0 clipped at -100;
//   |a|*(|b|*mean|x| - max|x|) >= 101  ==> all logits clip -> softmax uniform
//   -> out = mean_c(x). Fallback: exact tanh path (rare).
// ---------------------------------------------------------------------------
__global__ __launch_bounds__(256, 8) void dsf_fused_kernel(
    const float* __restrict__ x,
    const float* __restrict__ wgt,
    const float* __restrict__ bias,
    float* __restrict__ out) {

    // [c&31][pos*2 + (c>>5)], stride 62 floats (248B) per pair-row:
    // LDS.64 at lane*62*4B -> bank-pair (lane*31+pos)%32, conflict-free.
    __shared__ float tile2[32 * 62];   // 7.75 KB
    __shared__ float wp[1152];         // repacked [o][tap][64]  4.5 KB

    int tid = threadIdx.x;
    int p0  = blockIdx.x * 8;
    int b   = p0 >> 12;
    int hw0 = p0 & 4095;
    int h   = hw0 >> 6;
    int w0  = hw0 & 63;                // multiple of 8
    const float* xb = x + b * 262144;

    // ---- Phase 1a: halo tile. item q=(c,r,half): one aligned float4 + halo.
    #pragma unroll
    for (int k = 0; k < 2; k++) {
        int q = tid + k * 256;
        if (q < 384) {
            int c  = q / 6;
            int rm = q - c * 6;
            int r  = rm >> 1;
            int hf = rm & 1;
            int hh = h + r - 1;
            bool rowok = (unsigned)hh < 64u;
            const float* src = xb + c * 4096 + hh * 64;

            float4 v = make_float4(0.f, 0.f, 0.f, 0.f);
            if (rowok)
                v = *reinterpret_cast<const float4*>(src + w0 + hf * 4);

            float* d = &tile2[(c & 31) * 62 + (c >> 5)];
            int pb = r * 10 + 1 + hf * 4;
            d[(pb + 0) * 2] = v.x;
            d[(pb + 1) * 2] = v.y;
            d[(pb + 2) * 2] = v.z;
            d[(pb + 3) * 2] = v.w;

            int ww = hf ? (w0 + 8) : (w0 - 1);
            float hv = 0.0f;
            if (rowok && (unsigned)ww < 64u) hv = src[ww];
            d[(r * 10 + (hf ? 9 : 0)) * 2] = hv;
        }
    }
    // ---- Phase 1b: weights, repacked to [o][tap][c-pair] float2 layout.
    {
        const float4* gw = reinterpret_cast<const float4*>(wgt);
        #pragma unroll
        for (int k = 0; k < 2; k++) {
            int e4 = tid + k * 256;
            if (e4 < 288) {
                float4 w4 = gw[e4];
                float wv[4] = {w4.x, w4.y, w4.z, w4.w};
                int e = e4 * 4;
                #pragma unroll
                for (int j = 0; j < 4; j++) {
                    int ej = e + j;
                    int o  = (ej >= 576) ? 1 : 0;
                    int rm = ej - o * 576;
                    int c  = rm / 9;
                    int t  = rm - c * 9;
                    wp[(o * 9 + t) * 64 + (c & 31) * 2 + (c >> 5)] = wv[j];
                }
            }
        }
    }
    float b0 = __ldg(&bias[0]);
    float b1 = __ldg(&bias[1]);
    __syncthreads();

    int wid  = tid >> 5;   // pixel within block (0..7)
    int lane = tid & 31;

    // ---- Phase 2: conv via float2 pairs (channels lane, lane+32) ----------
    const float2* t2 = reinterpret_cast<const float2*>(&tile2[lane * 62]);
    const float2* w2 = reinterpret_cast<const float2*>(wp);

    float a00 = 0.f, a01 = 0.f, a10 = 0.f, a11 = 0.f;
    #pragma unroll
    for (int r = 0; r < 3; r++) {
        #pragma unroll
        for (int cc = 0; cc < 3; cc++) {
            int tap = r * 3 + cc;
            float2 v  = t2[r * 10 + wid + cc];
            float2 W0 = w2[tap * 32 + lane];
            float2 W1 = w2[(9 + tap) * 32 + lane];
            a00 = fmaf(v.x, W0.x, a00);
            a01 = fmaf(v.y, W0.y, a01);
            a10 = fmaf(v.x, W1.x, a10);
            a11 = fmaf(v.y, W1.y, a11);
        }
    }
    float a0 = a00 + a01;
    float a1 = a10 + a11;

    // ---- Channel values + fused butterfly (conv + stats, one chain) -------
    float2 xj = t2[11 + wid];          // center pixel, channels (lane, lane+32)
    float xj0 = xj.x, xj1 = xj.y;

    float ssum = xj0 + xj1;
    float sabs = fabsf(xj0) + fabsf(xj1);
    float smax = fmaxf(fabsf(xj0), fabsf(xj1));
    #pragma unroll
    for (int o = 16; o > 0; o >>= 1) {
        a0   += __shfl_xor_sync(0xffffffffu, a0, o);
        a1   += __shfl_xor_sync(0xffffffffu, a1, o);
        ssum += __shfl_xor_sync(0xffffffffu, ssum, o);
        sabs += __shfl_xor_sync(0xffffffffu, sabs, o);
        smax  = fmaxf(smax, __shfl_xor_sync(0xffffffffu, smax, o));
    }

    float alpha = MAXR * tanhf(a0 + b0);
    float beta  = MAXR * tanhf(a1 + b1);

    // ---- Screen C0: all logits provably clip to -100 -> uniform softmax ---
    if (fabsf(alpha) * (fabsf(beta) * (sabs * (1.0f / 64.0f)) - smax) >= 101.0f) {
        if (lane == 0) out[p0 + wid] = ssum * (1.0f / 64.0f);
        return;
    }

    // ---- Exact path: full tanh interaction + softmax (rare) ---------------
    float ab  = alpha * beta;
    float nc0 = -alpha * xj0;
    float nc1 = -alpha * xj1;

    float acc0 = 0.0f, acc1 = 0.0f;
    const float* xc = &tile2[(11 + wid) * 2];
    #pragma unroll
    for (int g = 0; g < 2; g++) {
        #pragma unroll 8
        for (int i = 0; i < 32; i++) {
            float xi = xc[i * 62 + g];   // LDS broadcast
            float z0 = fmaf(ab, xi, nc0);
            float z1 = fmaf(ab, xi, nc1);
            acc0 = fmaf(z0, tanh_fast(z0), acc0);
            acc1 = fmaf(z1, tanh_fast(z1), acc1);
        }
    }

    float l0 = fminf(fmaxf(acc0 * (-1.0f / 64.0f), -MAXR), MAXR);
    float l1 = fminf(fmaxf(acc1 * (-1.0f / 64.0f), -MAXR), MAXR);

    float m = fmaxf(l0, l1);
    #pragma unroll
    for (int o = 16; o > 0; o >>= 1)
        m = fmaxf(m, __shfl_xor_sync(0xffffffffu, m, o));

    float e0 = __expf(l0 - m);
    float e1 = __expf(l1 - m);
    float num = fmaf(xj0, e0, xj1 * e1);
    float den = e0 + e1;
    #pragma unroll
    for (int o = 16; o > 0; o >>= 1) {
        num += __shfl_xor_sync(0xffffffffu, num, o);
        den += __shfl_xor_sync(0xffffffffu, den, o);
    }

    if (lane == 0) out[p0 + wid] = num / den;
}

extern "C" void kernel_launch(void* const* d_in, const int* in_sizes, int n_in,
                              void* d_out, int out_size) {
    const float* x    = (const float*)d_in[0];
    const float* w    = (const float*)d_in[1];
    const float* bias = (const float*)d_in[2];
    float* out        = (float*)d_out;

    dsf_fused_kernel<<<2048, 256>>>(x, w, bias, out);
}

// round 8
// speedup vs baseline: 1.0019x; 1.0019x over previous
#include <cuda_runtime.h>

#define MAXR 100.0f

__device__ __forceinline__ float tanh_fast(float x) {
    float r;
    asm("tanh.approx.f32 %0, %1;" : "=f"(r) : "f"(x));
    return r;
}

// ---------------------------------------------------------------------------
// Fused kernel, per block = 16 consecutive same-row pixels (b, h, w0..w0+15).
// 512 threads = 16 warps; warp = pixel. Amortizes the 1152-float conv-weight
// load (previously 2.3x the whole input in DRAM traffic) over 2x the pixels.
// Phase 1: halo tile (64ch x 3row x 18col) via aligned float4 + halo scalars;
//          weights copied straight (no repack - R7 showed repack cost > win).
// Phase 2: warp-per-pixel 3x3 conv -> alpha, beta; fused butterfly also
//          reduces ssum/sabs/smax channel stats.
// Screen C0: logit_j = -|a|*mean_i(|d|*tanh(|a d|)) <= 0 clipped at -100;
//   |a|*(|b|*mean|x| - max|x|) >= 101 ==> all logits clip -> softmax uniform
//   -> out = mean_c(x). Fallback: exact tanh path (rare).
// ---------------------------------------------------------------------------
__global__ __launch_bounds__(512, 4) void dsf_fused_kernel(
    const float* __restrict__ x,
    const float* __restrict__ wgt,
    const float* __restrict__ bias,
    float* __restrict__ out) {

    __shared__ float tile[64][57];  // [c][r*18+cc]; 57 coprime 32 => no confl.
    __shared__ float sw[1152];      // conv weights [2][64][3][3], straight

    int tid = threadIdx.x;
    int p0  = blockIdx.x * 16;
    int b   = p0 >> 12;
    int hw0 = p0 & 4095;
    int h   = hw0 >> 6;
    int w0  = hw0 & 63;             // multiple of 16 -> float4 aligned
    const float* xb = x + b * 262144;

    // ---- Phase 1a: tile. item q=(c, r, f): one aligned float4 (4 center
    //      cols) ; f==0 also left halo, f==3 also right halo. ---------------
    #pragma unroll
    for (int k = 0; k < 2; k++) {
        int q = tid + k * 512;
        if (q < 768) {
            int c  = q / 12;           // mul-shift
            int rm = q - c * 12;
            int r  = rm >> 2;
            int f  = rm & 3;
            int hh = h + r - 1;
            bool rowok = (unsigned)hh < 64u;
            const float* src = xb + c * 4096 + hh * 64;

            float4 v = make_float4(0.f, 0.f, 0.f, 0.f);
            if (rowok)
                v = *reinterpret_cast<const float4*>(src + w0 + f * 4);
            float* d = &tile[c][r * 18 + 1 + f * 4];
            d[0] = v.x; d[1] = v.y; d[2] = v.z; d[3] = v.w;

            if (f == 0) {
                int ww = w0 - 1;
                float hv = 0.0f;
                if (rowok && (unsigned)ww < 64u) hv = src[ww];
                tile[c][r * 18] = hv;
            } else if (f == 3) {
                int ww = w0 + 16;
                float hv = 0.0f;
                if (rowok && (unsigned)ww < 64u) hv = src[ww];
                tile[c][r * 18 + 17] = hv;
            }
        }
    }
    // ---- Phase 1b: weights, straight float4 copy (288 float4). ------------
    if (tid < 288) {
        reinterpret_cast<float4*>(sw)[tid] =
            reinterpret_cast<const float4*>(wgt)[tid];
    }
    float b0 = __ldg(&bias[0]);
    float b1 = __ldg(&bias[1]);
    __syncthreads();

    int wid  = tid >> 5;   // pixel within block (0..15)
    int lane = tid & 31;

    // ---- Phase 2: 3x3 conv for this warp's pixel --------------------------
    float a0 = 0.0f, a1 = 0.0f;
    #pragma unroll
    for (int g = 0; g < 2; g++) {
        int c = lane + g * 32;
        const float* t  = &tile[c][0];
        const float* W0 = &sw[c * 9];
        const float* W1 = &sw[576 + c * 9];
        #pragma unroll
        for (int r = 0; r < 3; r++) {
            #pragma unroll
            for (int cc = 0; cc < 3; cc++) {
                float v = t[r * 18 + wid + cc];
                a0 = fmaf(v, W0[r * 3 + cc], a0);
                a1 = fmaf(v, W1[r * 3 + cc], a1);
            }
        }
    }

    // ---- Channel values + fused butterfly (conv + stats, one chain) -------
    const int ctr = 19 + wid;       // r=1 (offset 18) + halo 1 + wid
    float xj0 = tile[lane][ctr];
    float xj1 = tile[lane + 32][ctr];

    float ssum = xj0 + xj1;
    float sabs = fabsf(xj0) + fabsf(xj1);
    float smax = fmaxf(fabsf(xj0), fabsf(xj1));
    #pragma unroll
    for (int o = 16; o > 0; o >>= 1) {
        a0   += __shfl_xor_sync(0xffffffffu, a0, o);
        a1   += __shfl_xor_sync(0xffffffffu, a1, o);
        ssum += __shfl_xor_sync(0xffffffffu, ssum, o);
        sabs += __shfl_xor_sync(0xffffffffu, sabs, o);
        smax  = fmaxf(smax, __shfl_xor_sync(0xffffffffu, smax, o));
    }

    float alpha = MAXR * tanhf(a0 + b0);
    float beta  = MAXR * tanhf(a1 + b1);

    // ---- Screen C0: all logits provably clip to -100 -> uniform softmax ---
    if (fabsf(alpha) * (fabsf(beta) * (sabs * (1.0f / 64.0f)) - smax) >= 101.0f) {
        if (lane == 0) out[p0 + wid] = ssum * (1.0f / 64.0f);
        return;
    }

    // ---- Exact path: full tanh interaction + softmax (rare) ---------------
    float ab  = alpha * beta;
    float nc0 = -alpha * xj0;
    float nc1 = -alpha * xj1;
    const float* xc = &tile[0][ctr];

    float acc0 = 0.0f, acc1 = 0.0f;
    #pragma unroll 8
    for (int i = 0; i < 64; i++) {
        float xi = xc[i * 57];       // LDS broadcast
        float z0 = fmaf(ab, xi, nc0);
        float z1 = fmaf(ab, xi, nc1);
        acc0 = fmaf(z0, tanh_fast(z0), acc0);
        acc1 = fmaf(z1, tanh_fast(z1), acc1);
    }

    float l0 = fminf(fmaxf(acc0 * (-1.0f / 64.0f), -MAXR), MAXR);
    float l1 = fminf(fmaxf(acc1 * (-1.0f / 64.0f), -MAXR), MAXR);

    float m = fmaxf(l0, l1);
    #pragma unroll
    for (int o = 16; o > 0; o >>= 1)
        m = fmaxf(m, __shfl_xor_sync(0xffffffffu, m, o));

    float e0 = __expf(l0 - m);
    float e1 = __expf(l1 - m);
    float num = fmaf(xj0, e0, xj1 * e1);
    float den = e0 + e1;
    #pragma unroll
    for (int o = 16; o > 0; o >>= 1) {
        num += __shfl_xor_sync(0xffffffffu, num, o);
        den += __shfl_xor_sync(0xffffffffu, den, o);
    }

    if (lane == 0) out[p0 + wid] = num / den;
}

extern "C" void kernel_launch(void* const* d_in, const int* in_sizes, int n_in,
                              void* d_out, int out_size) {
    const float* x    = (const float*)d_in[0];
    const float* w    = (const float*)d_in[1];
    const float* bias = (const float*)d_in[2];
    float* out        = (float*)d_out;

    dsf_fused_kernel<<<1024, 512>>>(x, w, bias, out);
}